// round 13
// baseline (speedup 1.0000x reference)
#include <cuda_runtime.h>
#include <cuda_bf16.h>
#include <cuda_fp16.h>
#include <math.h>
#include <stdint.h>

#define LSEQ 2048
#define BATCH 4
#define DMODEL 512
#define NHEAD 8
#define DKH 64
#define NLAYER 4
#define DFFN 2048
#define MROWS (LSEQ * BATCH)   // 8192
#define NVOCAB 32000

// ---------------- scratch (device globals; no allocation allowed) ----------------
__device__ float g_x[MROWS * DMODEL];
__device__ float g_t[MROWS * DMODEL];                       // low half used as fp16 t
__device__ __nv_bfloat16 g_xs[2 * MROWS * DMODEL];          // x16 fp16 (half used)
__device__ __nv_bfloat16 g_qkvs[2 * MROWS * 3 * DMODEL];    // qkv fp16 (half used)
__device__ __nv_bfloat16 g_cs[2 * MROWS * DMODEL];          // ctx16 fp16 (half used)
__device__ __nv_bfloat16 g_ahi[MROWS * DFFN];               // ff fp16

// weight storage (fp16 single), element offsets:
#define WQKV0 0                 // fused [NLAYER][1536][512]
#define WO0 3145728
#define W10 4194304
#define W20 8388608
#define WD0 12582912
#define WTOT 28966912
__device__ __nv_bfloat16 g_whi[WTOT];

// ---------------- helpers ----------------
__device__ __forceinline__ uint32_t s2u(const void* p) {
    uint32_t a;
    asm("{ .reg .u64 t; cvta.to.shared.u64 t, %1; cvt.u32.u64 %0, t; }" : "=r"(a) : "l"(p));
    return a;
}
__device__ __forceinline__ void cpa16(uint32_t d, const void* s) {
    asm volatile("cp.async.cg.shared.global [%0], [%1], 16;" :: "r"(d), "l"(s));
}
__device__ __forceinline__ uint32_t h2pack(float x, float y) {
    __half2 t = __floats2half2_rn(x, y);
    return *(uint32_t*)&t;
}

#define LDSM4(r, a) \
    asm volatile("ldmatrix.sync.aligned.m8n8.x4.shared.b16 {%0,%1,%2,%3}, [%4];" \
        : "=r"((r)[0]), "=r"((r)[1]), "=r"((r)[2]), "=r"((r)[3]) : "r"(a))
#define LDSM4T(r, a) \
    asm volatile("ldmatrix.sync.aligned.m8n8.x4.trans.shared.b16 {%0,%1,%2,%3}, [%4];" \
        : "=r"((r)[0]), "=r"((r)[1]), "=r"((r)[2]), "=r"((r)[3]) : "r"(a))

#define MMAF16(c, a, b0, b1) \
    asm volatile("mma.sync.aligned.m16n8k16.row.col.f32.f16.f16.f32 " \
        "{%0,%1,%2,%3}, {%4,%5,%6,%7}, {%8,%9}, {%0,%1,%2,%3};" \
        : "+f"((c)[0]), "+f"((c)[1]), "+f"((c)[2]), "+f"((c)[3]) \
        : "r"((a)[0]), "r"((a)[1]), "r"((a)[2]), "r"((a)[3]), "r"(b0), "r"(b1))

// ---------------- fp32 -> fp16 single weight converts ----------------
__global__ void __launch_bounds__(256) cvt16(__half* __restrict__ dst,
                                             const float* __restrict__ src,
                                             int n4)
{
    int i = blockIdx.x * 256 + threadIdx.x;
    if (i >= n4) return;
    float4 v = ((const float4*)src)[i];
    ((uint32_t*)dst)[2 * i + 0] = h2pack(v.x, v.y);
    ((uint32_t*)dst)[2 * i + 1] = h2pack(v.z, v.w);
}

// strided QKV convert: src [NLAYER][512][512] -> dst layer stride 1536*512
__global__ void __launch_bounds__(256) cvt16_qkv(__half* __restrict__ dst,
                                                 const float* __restrict__ src,
                                                 float scale, int region2)
{
    int i = blockIdx.x * 256 + threadIdx.x;     // 262144 float4s total
    float4 v = ((const float4*)src)[i];
    v.x *= scale; v.y *= scale; v.z *= scale; v.w *= scale;
    int l = i >> 16, w = i & 65535;
    int di = l * 393216 + region2 + 2 * w;      // uint32 units
    ((uint32_t*)dst)[di + 0] = h2pack(v.x, v.y);
    ((uint32_t*)dst)[di + 1] = h2pack(v.z, v.w);
}

// ---------------- fp16 1-term GEMM: C = A * B^T (+bias,+relu) ----------------
// BM=128, BN=256, BK=64; 256 threads; warp 64x64; double buffered; 2 CTAs/SM.
// OUTM: 0 = fp32 C, 1 = fp16 O16
#define T1S 144                                  // 128B data + 16B pad
#define T1_A_TILE (128 * T1S)                    // 18432
#define T1_B_TILE (256 * T1S)                    // 36864
#define T1_STAGE (T1_A_TILE + T1_B_TILE)         // 55296
#define GEMM1_SMEM (2 * T1_STAGE)                // 110592 -> 2 CTAs/SM
#define OFF1_B T1_A_TILE

template <bool BIAS, bool RELU, int OUTM>
__global__ void __launch_bounds__(256, 2) gemm_1t(float* __restrict__ C,
                                                  __half* __restrict__ O16,
                                                  const __half* __restrict__ A,
                                                  const __half* __restrict__ B,
                                                  const float* __restrict__ bias,
                                                  int M, int N, int K)
{
    extern __shared__ char smem[];
    const uint32_t sb = s2u(smem);
    const int tid = threadIdx.x;
    const int warp = tid >> 5, lane = tid & 31;
    const int bm = blockIdx.y * 128;
    const int bn = blockIdx.x * 256;
    const int warp_m = warp >> 2;
    const int warp_n = warp & 3;
    const int nch = K >> 6;                      // K/64

    const __half* pA = A + (size_t)bm * K;
    const __half* pB = B + (size_t)bn * K;

    auto load_stage = [&](uint32_t st, int k0) {
        // A: 128 rows x 8 segs of 16B
#pragma unroll
        for (int j = 0; j < 4; j++) {
            int idx = tid + j * 256;
            int r = idx >> 3, seg = idx & 7;
            cpa16(st + r * T1S + seg * 16, pA + (size_t)r * K + k0 + seg * 8);
        }
        // B: 256 rows x 8 segs
#pragma unroll
        for (int j = 0; j < 8; j++) {
            int idx = tid + j * 256;
            int r = idx >> 3, seg = idx & 7;
            cpa16(st + OFF1_B + r * T1S + seg * 16, pB + (size_t)r * K + k0 + seg * 8);
        }
    };

    float acc[4][8][4];
#pragma unroll
    for (int i = 0; i < 4; i++)
#pragma unroll
        for (int j = 0; j < 8; j++)
#pragma unroll
            for (int q = 0; q < 4; q++) acc[i][j][q] = 0.f;

    const int g = lane >> 3, lr = lane & 7;
    const int a_row = lr + (g & 1) * 8;
    const int a_k8 = g >> 1;
    const int b_row = lr + (g >> 1) * 8;
    const int b_k8 = g & 1;

    load_stage(sb, 0);
    asm volatile("cp.async.commit_group;" ::: "memory");

    for (int i = 0; i < nch; i++) {
        const uint32_t st = sb + (i & 1) * T1_STAGE;
        __syncthreads();
        if (i + 1 < nch) load_stage(sb + ((i + 1) & 1) * T1_STAGE, (i + 1) * 64);
        asm volatile("cp.async.commit_group;" ::: "memory");
        asm volatile("cp.async.wait_group 1;" ::: "memory");
        __syncthreads();

#pragma unroll
        for (int ks = 0; ks < 4; ks++) {
            uint32_t ah[4][4];
#pragma unroll
            for (int mi = 0; mi < 4; mi++) {
                uint32_t aaddr = st + (warp_m * 64 + mi * 16 + a_row) * T1S +
                                 ks * 32 + a_k8 * 16;
                LDSM4(ah[mi], aaddr);
            }
#pragma unroll
            for (int ng = 0; ng < 4; ng++) {
                uint32_t bfr[4];
                uint32_t baddr = st + OFF1_B + (warp_n * 64 + ng * 16 + b_row) * T1S +
                                 ks * 32 + b_k8 * 16;
                LDSM4(bfr, baddr);
#pragma unroll
                for (int mi = 0; mi < 4; mi++) {
                    MMAF16(acc[mi][2 * ng], ah[mi], bfr[0], bfr[1]);
                    MMAF16(acc[mi][2 * ng + 1], ah[mi], bfr[2], bfr[3]);
                }
            }
        }
    }

    const int tm = lane >> 2, tn = (lane & 3) * 2;
#pragma unroll
    for (int mi = 0; mi < 4; mi++) {
#pragma unroll
        for (int nj = 0; nj < 8; nj++) {
            const float* a4 = acc[mi][nj];
            int row0 = bm + warp_m * 64 + mi * 16 + tm;
            int col = bn + warp_n * 64 + nj * 8 + tn;
            float b0 = 0.f, b1 = 0.f;
            if (BIAS) { b0 = bias[col]; b1 = bias[col + 1]; }
            float v0 = a4[0] + b0, v1 = a4[1] + b1;
            float v2 = a4[2] + b0, v3 = a4[3] + b1;
            if (RELU) {
                v0 = fmaxf(v0, 0.f); v1 = fmaxf(v1, 0.f);
                v2 = fmaxf(v2, 0.f); v3 = fmaxf(v3, 0.f);
            }
            if (OUTM == 0) {
                *(float2*)(C + (size_t)row0 * N + col) = make_float2(v0, v1);
                *(float2*)(C + (size_t)(row0 + 8) * N + col) = make_float2(v2, v3);
            } else {
                *(uint32_t*)(O16 + (size_t)row0 * N + col) = h2pack(v0, v1);
                *(uint32_t*)(O16 + (size_t)(row0 + 8) * N + col) = h2pack(v2, v3);
            }
        }
    }
}

// ---------------- embedding + positional encoding (fp32 + fp16 out) ----------------
__global__ void __launch_bounds__(128) embed_kernel(float* __restrict__ x,
                                                    __half* __restrict__ x16,
                                                    const int* __restrict__ tok,
                                                    const float* __restrict__ emb)
{
    int m = blockIdx.x;
    int l = m >> 2;
    int t = tok[m];
    const float sq = 22.627416997969522f;
    const double nlog = 9.210340371976184;
#pragma unroll
    for (int j = 0; j < 4; j++) {
        int d = threadIdx.x + j * 128;
        int i = d >> 1;
        float freqf = (float)exp(-(double)(2 * i) * (nlog / 512.0));
        float angf = (float)l * freqf;
        double ang = (double)angf;
        float pe = (d & 1) ? (float)cos(ang) : (float)sin(ang);
        float v = emb[(size_t)t * DMODEL + d] * sq + pe;
        x[(size_t)m * DMODEL + d] = v;
        x16[(size_t)m * DMODEL + d] = __float2half(v);
    }
}

// ---------------- fp16 flash attention (causal, 1-term), 64-row KV stages --------
#define QKVSTR 1536
#define AT_S 144
#define AQ_B (128 * AT_S)          // 18432
#define AKV_TILE (64 * AT_S)       // 9216
#define AKV_STAGE (2 * AKV_TILE)   // 18432 (K + V)
#define ATTN_SMEM (AQ_B + 2 * AKV_STAGE)   // 55296 -> 2 CTAs/SM

__global__ void __launch_bounds__(256) attn_mma(
    __half* __restrict__ ctx16,
    const __half* __restrict__ qkv16)
{
    extern __shared__ char smem[];
    const uint32_t sb = s2u(smem);
    const int tid = threadIdx.x, warp = tid >> 5, lane = tid & 31;
    const int bx = blockIdx.x, b = blockIdx.y, h = blockIdx.z;
    const int l0 = bx * 128;
    const int ntiles = 2 * bx + 2;

    const uint32_t sQ = sb;
    const uint32_t sKV = sb + AQ_B;

    // load Q tile: 128 rows x 8 segs of 16B
#pragma unroll
    for (int t = 0; t < 4; t++) {
        int idx = tid + t * 256;
        int row = idx >> 3, seg = idx & 7;
        cpa16(sQ + row * AT_S + seg * 16,
              qkv16 + ((size_t)(l0 + row) * 4 + b) * QKVSTR + h * 64 + seg * 8);
    }
    asm volatile("cp.async.commit_group;" ::: "memory");

    auto load_kv = [&](int s, int jt) {
        uint32_t st = sKV + s * AKV_STAGE;
#pragma unroll
        for (int t = 0; t < 4; t++) {
            int idx = tid + t * 256;
            int arr = idx >> 9;            // 0=K, 1=V
            int row = (idx >> 3) & 63;
            int seg = idx & 7;
            int coff = 512 + arr * 512;
            cpa16(st + arr * AKV_TILE + row * AT_S + seg * 16,
                  qkv16 + ((size_t)(jt * 64 + row) * 4 + b) * QKVSTR + coff + h * 64 + seg * 8);
        }
    };
    load_kv(0, 0);
    asm volatile("cp.async.commit_group;" ::: "memory");

    const int a_row = (lane & 7) + ((lane >> 3) & 1) * 8;
    const int a_k8 = lane >> 4;
    const int b_row = (lane & 7) + (lane >> 4) * 8;
    const int b_k8 = (lane >> 3) & 1;

    uint32_t qf[4][4];
    float ctx[8][4];
#pragma unroll
    for (int i = 0; i < 8; i++)
#pragma unroll
        for (int j = 0; j < 4; j++) ctx[i][j] = 0.f;
    float m0 = -INFINITY, m1 = -INFINITY, l0s = 0.f, l1s = 0.f;

    for (int jt = 0; jt < ntiles; jt++) {
        const uint32_t st = sKV + (jt & 1) * AKV_STAGE;
        __syncthreads();
        if (jt + 1 < ntiles) {
            load_kv((jt + 1) & 1, jt + 1);
            asm volatile("cp.async.commit_group;" ::: "memory");
            asm volatile("cp.async.wait_group 1;" ::: "memory");
        } else {
            asm volatile("cp.async.wait_group 0;" ::: "memory");
        }
        __syncthreads();

        if (jt == 0) {
#pragma unroll
            for (int kb = 0; kb < 4; kb++) {
                uint32_t qa = sQ + (warp * 16 + a_row) * AT_S + (kb * 2 + a_k8) * 16;
                LDSM4(qf[kb], qa);
            }
        }

        // S = Q K^T (1 term)
        float S[8][4];
#pragma unroll
        for (int i = 0; i < 8; i++)
#pragma unroll
            for (int j = 0; j < 4; j++) S[i][j] = 0.f;
#pragma unroll
        for (int kb = 0; kb < 4; kb++) {
#pragma unroll
            for (int ng = 0; ng < 4; ng++) {
                uint32_t kf[4];
                uint32_t ka = st + (ng * 16 + b_row) * AT_S + (kb * 2 + b_k8) * 16;
                LDSM4(kf, ka);
                int nb = ng * 2;
                MMAF16(S[nb], qf[kb], kf[0], kf[1]);
                MMAF16(S[nb + 1], qf[kb], kf[2], kf[3]);
            }
        }

        const int qr0 = l0 + warp * 16 + (lane >> 2);
        const int qr1 = qr0 + 8;
        if (jt >= ntiles - 2) {
#pragma unroll
            for (int nb = 0; nb < 8; nb++) {
                int c = jt * 64 + nb * 8 + 2 * (lane & 3);
                if (c > qr0) S[nb][0] = -INFINITY;
                if (c + 1 > qr0) S[nb][1] = -INFINITY;
                if (c > qr1) S[nb][2] = -INFINITY;
                if (c + 1 > qr1) S[nb][3] = -INFINITY;
            }
        }

        // online softmax
        float mx0 = -INFINITY, mx1 = -INFINITY;
#pragma unroll
        for (int nb = 0; nb < 8; nb++) {
            mx0 = fmaxf(mx0, fmaxf(S[nb][0], S[nb][1]));
            mx1 = fmaxf(mx1, fmaxf(S[nb][2], S[nb][3]));
        }
        mx0 = fmaxf(mx0, __shfl_xor_sync(0xffffffffu, mx0, 1));
        mx0 = fmaxf(mx0, __shfl_xor_sync(0xffffffffu, mx0, 2));
        mx1 = fmaxf(mx1, __shfl_xor_sync(0xffffffffu, mx1, 1));
        mx1 = fmaxf(mx1, __shfl_xor_sync(0xffffffffu, mx1, 2));
        float nm0 = fmaxf(m0, mx0), nm1 = fmaxf(m1, mx1);
        float c0 = __expf(m0 - nm0), c1 = __expf(m1 - nm1);
        m0 = nm0; m1 = nm1;
        float s0 = 0.f, s1 = 0.f;
#pragma unroll
        for (int nb = 0; nb < 8; nb++) {
            S[nb][0] = __expf(S[nb][0] - nm0);
            S[nb][1] = __expf(S[nb][1] - nm0);
            S[nb][2] = __expf(S[nb][2] - nm1);
            S[nb][3] = __expf(S[nb][3] - nm1);
            s0 += S[nb][0] + S[nb][1];
            s1 += S[nb][2] + S[nb][3];
        }
        s0 += __shfl_xor_sync(0xffffffffu, s0, 1);
        s0 += __shfl_xor_sync(0xffffffffu, s0, 2);
        s1 += __shfl_xor_sync(0xffffffffu, s1, 1);
        s1 += __shfl_xor_sync(0xffffffffu, s1, 2);
        l0s = l0s * c0 + s0;
        l1s = l1s * c1 + s1;
#pragma unroll
        for (int nb = 0; nb < 8; nb++) {
            ctx[nb][0] *= c0; ctx[nb][1] *= c0;
            ctx[nb][2] *= c1; ctx[nb][3] *= c1;
        }

        // P fragments (fp16, values in [0,1])
        uint32_t ph[4][4];
#pragma unroll
        for (int kb = 0; kb < 4; kb++) {
            const float* sA = S[2 * kb];
            const float* sB = S[2 * kb + 1];
            ph[kb][0] = h2pack(sA[0], sA[1]);
            ph[kb][1] = h2pack(sA[2], sA[3]);
            ph[kb][2] = h2pack(sB[0], sB[1]);
            ph[kb][3] = h2pack(sB[2], sB[3]);
        }

        // ctx += P V (1 term); V via ldmatrix.trans
        const uint32_t vrow = (lane & 7) + ((lane >> 3) & 1) * 8;
        const uint32_t vcol16 = (lane >> 4) * 16;
#pragma unroll
        for (int kb = 0; kb < 4; kb++) {
#pragma unroll
            for (int ngd = 0; ngd < 4; ngd++) {
                uint32_t vb[4];
                uint32_t va = st + AKV_TILE + (kb * 16 + vrow) * AT_S + ngd * 32 + vcol16;
                LDSM4T(vb, va);
                int nd = ngd * 2;
                MMAF16(ctx[nd], ph[kb], vb[0], vb[1]);
                MMAF16(ctx[nd + 1], ph[kb], vb[2], vb[3]);
            }
        }
    }

    float inv0 = 1.f / l0s, inv1 = 1.f / l1s;
    const size_t mg0 = (size_t)(l0 + warp * 16 + (lane >> 2)) * 4 + b;
    const size_t mg1 = mg0 + 32;
#pragma unroll
    for (int nd = 0; nd < 8; nd++) {
        int col = h * 64 + nd * 8 + 2 * (lane & 3);
        *(uint32_t*)(ctx16 + mg0 * 512 + col) = h2pack(ctx[nd][0] * inv0, ctx[nd][1] * inv0);
        *(uint32_t*)(ctx16 + mg1 * 512 + col) = h2pack(ctx[nd][2] * inv1, ctx[nd][3] * inv1);
    }
}

// ---------------- fused residual-add + LayerNorm (2 rows/block, fp16 out) ----
// residual input y is fp16.
__global__ void __launch_bounds__(256) add_ln_kernel(float* __restrict__ x,
                                                     __half* __restrict__ x16,
                                                     const __half* __restrict__ y,
                                                     const float* __restrict__ a,
                                                     const float* __restrict__ b,
                                                     const float* __restrict__ fa,
                                                     const float* __restrict__ fb)
{
    const int tid = threadIdx.x;
    const int half = tid >> 7;           // 0 or 1 (row within block)
    const int t128 = tid & 127;
    const int m = blockIdx.x * 2 + half;
    const size_t base = (size_t)m * DMODEL;
    __shared__ float red[2][8];

    float v[4];
#pragma unroll
    for (int j = 0; j < 4; j++) {
        int d = t128 + j * 128;
        float xv = x[base + d];
        xv += __half2float(y[base + d]);
        v[j] = xv;
    }
    float s = v[0] + v[1] + v[2] + v[3];
#pragma unroll
    for (int o = 16; o > 0; o >>= 1) s += __shfl_xor_sync(0xffffffffu, s, o);
    if ((t128 & 31) == 0) red[half][t128 >> 5] = s;
    __syncthreads();
    float mean = (red[half][0] + red[half][1] + red[half][2] + red[half][3]) * (1.f / 512.f);

    float ss = 0.f;
#pragma unroll
    for (int j = 0; j < 4; j++) {
        float dm = v[j] - mean;
        ss += dm * dm;
    }
#pragma unroll
    for (int o = 16; o > 0; o >>= 1) ss += __shfl_xor_sync(0xffffffffu, ss, o);
    if ((t128 & 31) == 0) red[half][4 + (t128 >> 5)] = ss;
    __syncthreads();
    float var = (red[half][4] + red[half][5] + red[half][6] + red[half][7]) * (1.f / 511.f);
    float inv = 1.f / (sqrtf(var) + 1e-6f);

    float o4[4];
#pragma unroll
    for (int j = 0; j < 4; j++) {
        int d = t128 + j * 128;
        o4[j] = a[d] * (v[j] - mean) * inv + b[d];
    }

    if (fa) {
        __syncthreads();
        float s2 = o4[0] + o4[1] + o4[2] + o4[3];
#pragma unroll
        for (int o = 16; o > 0; o >>= 1) s2 += __shfl_xor_sync(0xffffffffu, s2, o);
        if ((t128 & 31) == 0) red[half][t128 >> 5] = s2;
        __syncthreads();
        float mean2 = (red[half][0] + red[half][1] + red[half][2] + red[half][3]) * (1.f / 512.f);
        float ss2 = 0.f;
#pragma unroll
        for (int j = 0; j < 4; j++) {
            float dm = o4[j] - mean2;
            ss2 += dm * dm;
        }
#pragma unroll
        for (int o = 16; o > 0; o >>= 1) ss2 += __shfl_xor_sync(0xffffffffu, ss2, o);
        if ((t128 & 31) == 0) red[half][4 + (t128 >> 5)] = ss2;
        __syncthreads();
        float var2 = (red[half][4] + red[half][5] + red[half][6] + red[half][7]) * (1.f / 511.f);
        float inv2 = 1.f / (sqrtf(var2) + 1e-6f);
#pragma unroll
        for (int j = 0; j < 4; j++) {
            int d = t128 + j * 128;
            o4[j] = fa[d] * (o4[j] - mean2) * inv2 + fb[d];
        }
    }

#pragma unroll
    for (int j = 0; j < 4; j++) {
        int d = t128 + j * 128;
        x[base + d] = o4[j];
        x16[base + d] = __float2half(o4[j]);
    }
}

// ---------------- orchestration ----------------
extern "C" void kernel_launch(void* const* d_in, const int* in_sizes, int n_in,
                              void* d_out, int out_size)
{
    (void)in_sizes; (void)n_in; (void)out_size;
    const int*   input = (const int*)  d_in[0];
    const float* emb   = (const float*)d_in[1];
    const float* Wq    = (const float*)d_in[2];
    const float* Wk    = (const float*)d_in[3];
    const float* Wv    = (const float*)d_in[4];
    const float* Wo    = (const float*)d_in[5];
    const float* w1    = (const float*)d_in[6];
    const float* b1    = (const float*)d_in[7];
    const float* w2    = (const float*)d_in[8];
    const float* b2    = (const float*)d_in[9];
    const float* ln1a  = (const float*)d_in[10];
    const float* ln1b  = (const float*)d_in[11];
    const float* ln2a  = (const float*)d_in[12];
    const float* ln2b  = (const float*)d_in[13];
    const float* fna   = (const float*)d_in[14];
    const float* fnb   = (const float*)d_in[15];
    const float* decW  = (const float*)d_in[16];
    const float* decb  = (const float*)d_in[17];
    float* out = (float*)d_out;

    float *x, *t;
    __nv_bfloat16 *xs, *qkvs, *cs, *ahi, *whi;
    cudaGetSymbolAddress((void**)&x,    g_x);
    cudaGetSymbolAddress((void**)&t,    g_t);
    cudaGetSymbolAddress((void**)&xs,   g_xs);
    cudaGetSymbolAddress((void**)&qkvs, g_qkvs);
    cudaGetSymbolAddress((void**)&cs,   g_cs);
    cudaGetSymbolAddress((void**)&ahi,  g_ahi);
    cudaGetSymbolAddress((void**)&whi,  g_whi);

    __half* x16 = (__half*)xs;
    __half* qkv16 = (__half*)qkvs;
    __half* c16 = (__half*)cs;
    __half* a16 = (__half*)ahi;
    __half* t16 = (__half*)t;
    __half* wh = (__half*)whi;

    cudaFuncSetAttribute(attn_mma, cudaFuncAttributeMaxDynamicSharedMemorySize, ATTN_SMEM);
    cudaFuncSetAttribute(gemm_1t<false, false, 1>, cudaFuncAttributeMaxDynamicSharedMemorySize, GEMM1_SMEM);
    cudaFuncSetAttribute(gemm_1t<true, true, 1>,   cudaFuncAttributeMaxDynamicSharedMemorySize, GEMM1_SMEM);
    cudaFuncSetAttribute(gemm_1t<true, false, 1>,  cudaFuncAttributeMaxDynamicSharedMemorySize, GEMM1_SMEM);
    cudaFuncSetAttribute(gemm_1t<true, false, 0>,  cudaFuncAttributeMaxDynamicSharedMemorySize, GEMM1_SMEM);

    // ---- side stream for weight converts (fork/join; graph-capturable) ----
    cudaStream_t s2;
    cudaStreamCreateWithFlags(&s2, cudaStreamNonBlocking);
    cudaEvent_t eFork, eQKV, eMid, eDec;
    cudaEventCreateWithFlags(&eFork, cudaEventDisableTiming);
    cudaEventCreateWithFlags(&eQKV,  cudaEventDisableTiming);
    cudaEventCreateWithFlags(&eMid,  cudaEventDisableTiming);
    cudaEventCreateWithFlags(&eDec,  cudaEventDisableTiming);

    cudaEventRecord(eFork, 0);
    cudaStreamWaitEvent(s2, eFork, 0);

    cvt16_qkv<<<1024, 256, 0, s2>>>(wh + WQKV0, Wq, 0.125f, 0);
    cvt16_qkv<<<1024, 256, 0, s2>>>(wh + WQKV0, Wk, 1.0f, 131072);
    cvt16_qkv<<<1024, 256, 0, s2>>>(wh + WQKV0, Wv, 1.0f, 262144);
    cudaEventRecord(eQKV, s2);
    cvt16<<<1024, 256, 0, s2>>>(wh + WO0, Wo, 1048576 / 4);
    cvt16<<<4096, 256, 0, s2>>>(wh + W10, w1, 4194304 / 4);
    cvt16<<<4096, 256, 0, s2>>>(wh + W20, w2, 4194304 / 4);
    cudaEventRecord(eMid, s2);
    cvt16<<<16000, 256, 0, s2>>>(wh + WD0, decW, 16384000 / 4);
    cudaEventRecord(eDec, s2);

    // main stream: embed runs concurrently with the cvt chain
    embed_kernel<<<MROWS, 128>>>(x, x16, input, emb);
    cudaStreamWaitEvent(0, eQKV, 0);     // QKV weights ready

    const dim3 gQKV(3 * DMODEL / 256, MROWS / 128);  // (6, 64)
    const dim3 gD(DMODEL / 256, MROWS / 128);        // (2, 64)
    const dim3 gF(DFFN / 256, MROWS / 128);          // (8, 64)
    const dim3 gV(NVOCAB / 256, MROWS / 128);        // (125, 64)
    const dim3 gAttn(LSEQ / 128, BATCH, NHEAD);

    for (int l = 0; l < NLAYER; l++) {
        const size_t qofs = (size_t)l * 1536 * 512;
        const size_t wofs = (size_t)l * DMODEL * DMODEL;
        const size_t f1 = (size_t)l * DFFN * DMODEL;
        const bool last = (l == NLAYER - 1);

        gemm_1t<false, false, 1><<<gQKV, 256, GEMM1_SMEM>>>(
            nullptr, qkv16, x16, wh + WQKV0 + qofs,
            nullptr, MROWS, 3 * DMODEL, DMODEL);

        attn_mma<<<gAttn, 256, ATTN_SMEM>>>(c16, qkv16);

        if (l == 0) cudaStreamWaitEvent(0, eMid, 0);   // Wo/w1/w2 ready

        gemm_1t<false, false, 1><<<gD, 256, GEMM1_SMEM>>>(
            nullptr, t16, c16, wh + WO0 + wofs,
            nullptr, MROWS, DMODEL, DMODEL);
        add_ln_kernel<<<MROWS / 2, 256>>>(x, x16, t16, ln1a + l * DMODEL, ln1b + l * DMODEL,
                                          nullptr, nullptr);

        gemm_1t<true, true, 1><<<gF, 256, GEMM1_SMEM>>>(
            nullptr, a16, x16, wh + W10 + f1,
            b1 + l * DFFN, MROWS, DFFN, DMODEL);
        gemm_1t<true, false, 1><<<gD, 256, GEMM1_SMEM>>>(
            nullptr, t16, a16, wh + W20 + f1,
            b2 + l * DMODEL, MROWS, DMODEL, DFFN);
        add_ln_kernel<<<MROWS / 2, 256>>>(x, x16, t16, ln2a + l * DMODEL, ln2b + l * DMODEL,
                                          last ? fna : nullptr, last ? fnb : nullptr);
    }

    cudaStreamWaitEvent(0, eDec, 0);     // decoder weights ready (join side stream)
    gemm_1t<true, false, 0><<<gV, 256, GEMM1_SMEM>>>(
        out, nullptr, x16, wh + WD0,
        decb, MROWS, NVOCAB, DMODEL);
}

// round 15
// speedup vs baseline: 2.1972x; 2.1972x over previous
#include <cuda_runtime.h>
#include <cuda_bf16.h>
#include <cuda_fp16.h>
#include <math.h>
#include <stdint.h>

#define LSEQ 2048
#define BATCH 4
#define DMODEL 512
#define NHEAD 8
#define DKH 64
#define NLAYER 4
#define DFFN 2048
#define MROWS (LSEQ * BATCH)   // 8192
#define NVOCAB 32000

// ---------------- scratch (device globals; no allocation allowed) ----------------
__device__ float g_x[MROWS * DMODEL];
__device__ float g_t[MROWS * DMODEL];                       // low half used as fp16 t
__device__ __nv_bfloat16 g_xs[2 * MROWS * DMODEL];          // x16 fp16 (half used)
__device__ __nv_bfloat16 g_qkvs[2 * MROWS * 3 * DMODEL];    // qkv fp16 (half used)
__device__ __nv_bfloat16 g_cs[2 * MROWS * DMODEL];          // ctx16 fp16 (half used)
__device__ __nv_bfloat16 g_ahi[MROWS * DFFN];               // ff fp16

// weight storage (fp16 single), element offsets:
#define WQKV0 0                 // fused [NLAYER][1536][512]
#define WO0 3145728
#define W10 4194304
#define W20 8388608
#define WD0 12582912
#define WTOT 28966912
__device__ __nv_bfloat16 g_whi[WTOT];

// ---------------- helpers ----------------
__device__ __forceinline__ uint32_t s2u(const void* p) {
    uint32_t a;
    asm("{ .reg .u64 t; cvta.to.shared.u64 t, %1; cvt.u32.u64 %0, t; }" : "=r"(a) : "l"(p));
    return a;
}
__device__ __forceinline__ void cpa16(uint32_t d, const void* s) {
    asm volatile("cp.async.cg.shared.global [%0], [%1], 16;" :: "r"(d), "l"(s));
}
__device__ __forceinline__ uint32_t h2pack(float x, float y) {
    __half2 t = __floats2half2_rn(x, y);
    return *(uint32_t*)&t;
}

#define LDSM4(r, a) \
    asm volatile("ldmatrix.sync.aligned.m8n8.x4.shared.b16 {%0,%1,%2,%3}, [%4];" \
        : "=r"((r)[0]), "=r"((r)[1]), "=r"((r)[2]), "=r"((r)[3]) : "r"(a))
#define LDSM4T(r, a) \
    asm volatile("ldmatrix.sync.aligned.m8n8.x4.trans.shared.b16 {%0,%1,%2,%3}, [%4];" \
        : "=r"((r)[0]), "=r"((r)[1]), "=r"((r)[2]), "=r"((r)[3]) : "r"(a))

#define MMAF16(c, a, b0, b1) \
    asm volatile("mma.sync.aligned.m16n8k16.row.col.f32.f16.f16.f32 " \
        "{%0,%1,%2,%3}, {%4,%5,%6,%7}, {%8,%9}, {%0,%1,%2,%3};" \
        : "+f"((c)[0]), "+f"((c)[1]), "+f"((c)[2]), "+f"((c)[3]) \
        : "r"((a)[0]), "r"((a)[1]), "r"((a)[2]), "r"((a)[3]), "r"(b0), "r"(b1))

// ---------------- fp32 -> fp16 single weight converts ----------------
__global__ void __launch_bounds__(256) cvt16(__half* __restrict__ dst,
                                             const float* __restrict__ src,
                                             int n4)
{
    int i = blockIdx.x * 256 + threadIdx.x;
    if (i >= n4) return;
    float4 v = ((const float4*)src)[i];
    ((uint32_t*)dst)[2 * i + 0] = h2pack(v.x, v.y);
    ((uint32_t*)dst)[2 * i + 1] = h2pack(v.z, v.w);
}

// strided QKV convert: src [NLAYER][512][512] -> dst layer stride 1536*512
__global__ void __launch_bounds__(256) cvt16_qkv(__half* __restrict__ dst,
                                                 const float* __restrict__ src,
                                                 float scale, int region2)
{
    int i = blockIdx.x * 256 + threadIdx.x;     // 262144 float4s total
    float4 v = ((const float4*)src)[i];
    v.x *= scale; v.y *= scale; v.z *= scale; v.w *= scale;
    int l = i >> 16, w = i & 65535;
    int di = l * 393216 + region2 + 2 * w;      // uint32 units
    ((uint32_t*)dst)[di + 0] = h2pack(v.x, v.y);
    ((uint32_t*)dst)[di + 1] = h2pack(v.z, v.w);
}

// ---------------- fp16 1-term GEMM: C = A * B^T (+bias,+relu) ----------------
// BM=128, BN=256, BK=128; 256 threads; warp 64x64; double buffered.
// OUTM: 0 = fp32 C, 1 = fp16 O16
#define T1S 272                                  // 256B data + 16B pad
#define T1_A_TILE (128 * T1S)                    // 34816
#define T1_B_TILE (256 * T1S)                    // 69632
#define T1_STAGE (T1_A_TILE + T1_B_TILE)         // 104448
#define GEMM1_SMEM (2 * T1_STAGE)                // 208896
#define OFF1_B T1_A_TILE

template <bool BIAS, bool RELU, int OUTM>
__global__ void __launch_bounds__(256) gemm_1t(float* __restrict__ C,
                                               __half* __restrict__ O16,
                                               const __half* __restrict__ A,
                                               const __half* __restrict__ B,
                                               const float* __restrict__ bias,
                                               int M, int N, int K)
{
    extern __shared__ char smem[];
    const uint32_t sb = s2u(smem);
    const int tid = threadIdx.x;
    const int warp = tid >> 5, lane = tid & 31;
    const int bm = blockIdx.y * 128;
    const int bn = blockIdx.x * 256;
    const int warp_m = warp >> 2;
    const int warp_n = warp & 3;
    const int nch = K >> 7;                      // K/128

    const __half* pA = A + (size_t)bm * K;
    const __half* pB = B + (size_t)bn * K;

    auto load_stage = [&](uint32_t st, int k0) {
#pragma unroll
        for (int j = 0; j < 8; j++) {
            int idx = tid + j * 256;
            int r = idx >> 4, seg = idx & 15;
            cpa16(st + r * T1S + seg * 16, pA + (size_t)r * K + k0 + seg * 8);
        }
#pragma unroll
        for (int j = 0; j < 16; j++) {
            int idx = tid + j * 256;
            int r = idx >> 4, seg = idx & 15;
            cpa16(st + OFF1_B + r * T1S + seg * 16, pB + (size_t)r * K + k0 + seg * 8);
        }
    };

    float acc[4][8][4];
#pragma unroll
    for (int i = 0; i < 4; i++)
#pragma unroll
        for (int j = 0; j < 8; j++)
#pragma unroll
            for (int q = 0; q < 4; q++) acc[i][j][q] = 0.f;

    const int g = lane >> 3, lr = lane & 7;
    const int a_row = lr + (g & 1) * 8;
    const int a_k8 = g >> 1;
    const int b_row = lr + (g >> 1) * 8;
    const int b_k8 = g & 1;

    load_stage(sb, 0);
    asm volatile("cp.async.commit_group;" ::: "memory");

    for (int i = 0; i < nch; i++) {
        const uint32_t st = sb + (i & 1) * T1_STAGE;
        __syncthreads();
        if (i + 1 < nch) load_stage(sb + ((i + 1) & 1) * T1_STAGE, (i + 1) * 128);
        asm volatile("cp.async.commit_group;" ::: "memory");
        asm volatile("cp.async.wait_group 1;" ::: "memory");
        __syncthreads();

#pragma unroll
        for (int ks = 0; ks < 8; ks++) {
            uint32_t ah[4][4];
#pragma unroll
            for (int mi = 0; mi < 4; mi++) {
                uint32_t aaddr = st + (warp_m * 64 + mi * 16 + a_row) * T1S +
                                 ks * 32 + a_k8 * 16;
                LDSM4(ah[mi], aaddr);
            }
#pragma unroll
            for (int ng = 0; ng < 4; ng++) {
                uint32_t bfr[4];
                uint32_t baddr = st + OFF1_B + (warp_n * 64 + ng * 16 + b_row) * T1S +
                                 ks * 32 + b_k8 * 16;
                LDSM4(bfr, baddr);
#pragma unroll
                for (int mi = 0; mi < 4; mi++) {
                    MMAF16(acc[mi][2 * ng], ah[mi], bfr[0], bfr[1]);
                    MMAF16(acc[mi][2 * ng + 1], ah[mi], bfr[2], bfr[3]);
                }
            }
        }
    }

    const int tm = lane >> 2, tn = (lane & 3) * 2;
#pragma unroll
    for (int mi = 0; mi < 4; mi++) {
#pragma unroll
        for (int nj = 0; nj < 8; nj++) {
            const float* a4 = acc[mi][nj];
            int row0 = bm + warp_m * 64 + mi * 16 + tm;
            int col = bn + warp_n * 64 + nj * 8 + tn;
            float b0 = 0.f, b1 = 0.f;
            if (BIAS) { b0 = bias[col]; b1 = bias[col + 1]; }
            float v0 = a4[0] + b0, v1 = a4[1] + b1;
            float v2 = a4[2] + b0, v3 = a4[3] + b1;
            if (RELU) {
                v0 = fmaxf(v0, 0.f); v1 = fmaxf(v1, 0.f);
                v2 = fmaxf(v2, 0.f); v3 = fmaxf(v3, 0.f);
            }
            if (OUTM == 0) {
                *(float2*)(C + (size_t)row0 * N + col) = make_float2(v0, v1);
                *(float2*)(C + (size_t)(row0 + 8) * N + col) = make_float2(v2, v3);
            } else {
                *(uint32_t*)(O16 + (size_t)row0 * N + col) = h2pack(v0, v1);
                *(uint32_t*)(O16 + (size_t)(row0 + 8) * N + col) = h2pack(v2, v3);
            }
        }
    }
}

// ---------------- embedding + positional encoding (fp32 + fp16 out) ----------------
__global__ void __launch_bounds__(128) embed_kernel(float* __restrict__ x,
                                                    __half* __restrict__ x16,
                                                    const int* __restrict__ tok,
                                                    const float* __restrict__ emb)
{
    int m = blockIdx.x;
    int l = m >> 2;
    int t = tok[m];
    const float sq = 22.627416997969522f;
    const double nlog = 9.210340371976184;
#pragma unroll
    for (int j = 0; j < 4; j++) {
        int d = threadIdx.x + j * 128;
        int i = d >> 1;
        float freqf = (float)exp(-(double)(2 * i) * (nlog / 512.0));
        float angf = (float)l * freqf;
        double ang = (double)angf;
        float pe = (d & 1) ? (float)cos(ang) : (float)sin(ang);
        float v = emb[(size_t)t * DMODEL + d] * sq + pe;
        x[(size_t)m * DMODEL + d] = v;
        x16[(size_t)m * DMODEL + d] = __float2half(v);
    }
}

// ---------------- fp16 flash attention (causal, 1-term), 64-row KV stages --------
#define QKVSTR 1536
#define AT_S 144
#define AQ_B (128 * AT_S)          // 18432
#define AKV_TILE (64 * AT_S)       // 9216
#define AKV_STAGE (2 * AKV_TILE)   // 18432 (K + V)
#define ATTN_SMEM (AQ_B + 2 * AKV_STAGE)   // 55296 -> 2 CTAs/SM

__global__ void __launch_bounds__(256) attn_mma(
    __half* __restrict__ ctx16,
    const __half* __restrict__ qkv16)
{
    extern __shared__ char smem[];
    const uint32_t sb = s2u(smem);
    const int tid = threadIdx.x, warp = tid >> 5, lane = tid & 31;
    const int bx = blockIdx.x, b = blockIdx.y, h = blockIdx.z;
    const int l0 = bx * 128;
    const int ntiles = 2 * bx + 2;

    const uint32_t sQ = sb;
    const uint32_t sKV = sb + AQ_B;

    // load Q tile: 128 rows x 8 segs of 16B
#pragma unroll
    for (int t = 0; t < 4; t++) {
        int idx = tid + t * 256;
        int row = idx >> 3, seg = idx & 7;
        cpa16(sQ + row * AT_S + seg * 16,
              qkv16 + ((size_t)(l0 + row) * 4 + b) * QKVSTR + h * 64 + seg * 8);
    }
    asm volatile("cp.async.commit_group;" ::: "memory");

    auto load_kv = [&](int s, int jt) {
        uint32_t st = sKV + s * AKV_STAGE;
#pragma unroll
        for (int t = 0; t < 4; t++) {
            int idx = tid + t * 256;
            int arr = idx >> 9;            // 0=K, 1=V
            int row = (idx >> 3) & 63;
            int seg = idx & 7;
            int coff = 512 + arr * 512;
            cpa16(st + arr * AKV_TILE + row * AT_S + seg * 16,
                  qkv16 + ((size_t)(jt * 64 + row) * 4 + b) * QKVSTR + coff + h * 64 + seg * 8);
        }
    };
    load_kv(0, 0);
    asm volatile("cp.async.commit_group;" ::: "memory");

    const int a_row = (lane & 7) + ((lane >> 3) & 1) * 8;
    const int a_k8 = lane >> 4;
    const int b_row = (lane & 7) + (lane >> 4) * 8;
    const int b_k8 = (lane >> 3) & 1;

    uint32_t qf[4][4];
    float ctx[8][4];
#pragma unroll
    for (int i = 0; i < 8; i++)
#pragma unroll
        for (int j = 0; j < 4; j++) ctx[i][j] = 0.f;
    float m0 = -INFINITY, m1 = -INFINITY, l0s = 0.f, l1s = 0.f;

    for (int jt = 0; jt < ntiles; jt++) {
        const uint32_t st = sKV + (jt & 1) * AKV_STAGE;
        __syncthreads();
        if (jt + 1 < ntiles) {
            load_kv((jt + 1) & 1, jt + 1);
            asm volatile("cp.async.commit_group;" ::: "memory");
            asm volatile("cp.async.wait_group 1;" ::: "memory");
        } else {
            asm volatile("cp.async.wait_group 0;" ::: "memory");
        }
        __syncthreads();

        if (jt == 0) {
#pragma unroll
            for (int kb = 0; kb < 4; kb++) {
                uint32_t qa = sQ + (warp * 16 + a_row) * AT_S + (kb * 2 + a_k8) * 16;
                LDSM4(qf[kb], qa);
            }
        }

        // S = Q K^T (1 term)
        float S[8][4];
#pragma unroll
        for (int i = 0; i < 8; i++)
#pragma unroll
            for (int j = 0; j < 4; j++) S[i][j] = 0.f;
#pragma unroll
        for (int kb = 0; kb < 4; kb++) {
#pragma unroll
            for (int ng = 0; ng < 4; ng++) {
                uint32_t kf[4];
                uint32_t ka = st + (ng * 16 + b_row) * AT_S + (kb * 2 + b_k8) * 16;
                LDSM4(kf, ka);
                int nb = ng * 2;
                MMAF16(S[nb], qf[kb], kf[0], kf[1]);
                MMAF16(S[nb + 1], qf[kb], kf[2], kf[3]);
            }
        }

        const int qr0 = l0 + warp * 16 + (lane >> 2);
        const int qr1 = qr0 + 8;
        if (jt >= ntiles - 2) {
#pragma unroll
            for (int nb = 0; nb < 8; nb++) {
                int c = jt * 64 + nb * 8 + 2 * (lane & 3);
                if (c > qr0) S[nb][0] = -INFINITY;
                if (c + 1 > qr0) S[nb][1] = -INFINITY;
                if (c > qr1) S[nb][2] = -INFINITY;
                if (c + 1 > qr1) S[nb][3] = -INFINITY;
            }
        }

        // online softmax
        float mx0 = -INFINITY, mx1 = -INFINITY;
#pragma unroll
        for (int nb = 0; nb < 8; nb++) {
            mx0 = fmaxf(mx0, fmaxf(S[nb][0], S[nb][1]));
            mx1 = fmaxf(mx1, fmaxf(S[nb][2], S[nb][3]));
        }
        mx0 = fmaxf(mx0, __shfl_xor_sync(0xffffffffu, mx0, 1));
        mx0 = fmaxf(mx0, __shfl_xor_sync(0xffffffffu, mx0, 2));
        mx1 = fmaxf(mx1, __shfl_xor_sync(0xffffffffu, mx1, 1));
        mx1 = fmaxf(mx1, __shfl_xor_sync(0xffffffffu, mx1, 2));
        float nm0 = fmaxf(m0, mx0), nm1 = fmaxf(m1, mx1);
        float c0 = __expf(m0 - nm0), c1 = __expf(m1 - nm1);
        m0 = nm0; m1 = nm1;
        float s0 = 0.f, s1 = 0.f;
#pragma unroll
        for (int nb = 0; nb < 8; nb++) {
            S[nb][0] = __expf(S[nb][0] - nm0);
            S[nb][1] = __expf(S[nb][1] - nm0);
            S[nb][2] = __expf(S[nb][2] - nm1);
            S[nb][3] = __expf(S[nb][3] - nm1);
            s0 += S[nb][0] + S[nb][1];
            s1 += S[nb][2] + S[nb][3];
        }
        s0 += __shfl_xor_sync(0xffffffffu, s0, 1);
        s0 += __shfl_xor_sync(0xffffffffu, s0, 2);
        s1 += __shfl_xor_sync(0xffffffffu, s1, 1);
        s1 += __shfl_xor_sync(0xffffffffu, s1, 2);
        l0s = l0s * c0 + s0;
        l1s = l1s * c1 + s1;
#pragma unroll
        for (int nb = 0; nb < 8; nb++) {
            ctx[nb][0] *= c0; ctx[nb][1] *= c0;
            ctx[nb][2] *= c1; ctx[nb][3] *= c1;
        }

        // P fragments (fp16, values in [0,1])
        uint32_t ph[4][4];
#pragma unroll
        for (int kb = 0; kb < 4; kb++) {
            const float* sA = S[2 * kb];
            const float* sB = S[2 * kb + 1];
            ph[kb][0] = h2pack(sA[0], sA[1]);
            ph[kb][1] = h2pack(sA[2], sA[3]);
            ph[kb][2] = h2pack(sB[0], sB[1]);
            ph[kb][3] = h2pack(sB[2], sB[3]);
        }

        // ctx += P V (1 term); V via ldmatrix.trans
        const uint32_t vrow = (lane & 7) + ((lane >> 3) & 1) * 8;
        const uint32_t vcol16 = (lane >> 4) * 16;
#pragma unroll
        for (int kb = 0; kb < 4; kb++) {
#pragma unroll
            for (int ngd = 0; ngd < 4; ngd++) {
                uint32_t vb[4];
                uint32_t va = st + AKV_TILE + (kb * 16 + vrow) * AT_S + ngd * 32 + vcol16;
                LDSM4T(vb, va);
                int nd = ngd * 2;
                MMAF16(ctx[nd], ph[kb], vb[0], vb[1]);
                MMAF16(ctx[nd + 1], ph[kb], vb[2], vb[3]);
            }
        }
    }

    float inv0 = 1.f / l0s, inv1 = 1.f / l1s;
    const size_t mg0 = (size_t)(l0 + warp * 16 + (lane >> 2)) * 4 + b;
    const size_t mg1 = mg0 + 32;
#pragma unroll
    for (int nd = 0; nd < 8; nd++) {
        int col = h * 64 + nd * 8 + 2 * (lane & 3);
        *(uint32_t*)(ctx16 + mg0 * 512 + col) = h2pack(ctx[nd][0] * inv0, ctx[nd][1] * inv0);
        *(uint32_t*)(ctx16 + mg1 * 512 + col) = h2pack(ctx[nd][2] * inv1, ctx[nd][3] * inv1);
    }
}

// ---------------- fused residual-add + LayerNorm (2 rows/block, fp16 out) ----
// residual input y is fp16.
__global__ void __launch_bounds__(256) add_ln_kernel(float* __restrict__ x,
                                                     __half* __restrict__ x16,
                                                     const __half* __restrict__ y,
                                                     const float* __restrict__ a,
                                                     const float* __restrict__ b,
                                                     const float* __restrict__ fa,
                                                     const float* __restrict__ fb)
{
    const int tid = threadIdx.x;
    const int half = tid >> 7;           // 0 or 1 (row within block)
    const int t128 = tid & 127;
    const int m = blockIdx.x * 2 + half;
    const size_t base = (size_t)m * DMODEL;
    __shared__ float red[2][8];

    float v[4];
#pragma unroll
    for (int j = 0; j < 4; j++) {
        int d = t128 + j * 128;
        float xv = x[base + d];
        xv += __half2float(y[base + d]);
        v[j] = xv;
    }
    float s = v[0] + v[1] + v[2] + v[3];
#pragma unroll
    for (int o = 16; o > 0; o >>= 1) s += __shfl_xor_sync(0xffffffffu, s, o);
    if ((t128 & 31) == 0) red[half][t128 >> 5] = s;
    __syncthreads();
    float mean = (red[half][0] + red[half][1] + red[half][2] + red[half][3]) * (1.f / 512.f);

    float ss = 0.f;
#pragma unroll
    for (int j = 0; j < 4; j++) {
        float dm = v[j] - mean;
        ss += dm * dm;
    }
#pragma unroll
    for (int o = 16; o > 0; o >>= 1) ss += __shfl_xor_sync(0xffffffffu, ss, o);
    if ((t128 & 31) == 0) red[half][4 + (t128 >> 5)] = ss;
    __syncthreads();
    float var = (red[half][4] + red[half][5] + red[half][6] + red[half][7]) * (1.f / 511.f);
    float inv = 1.f / (sqrtf(var) + 1e-6f);

    float o4[4];
#pragma unroll
    for (int j = 0; j < 4; j++) {
        int d = t128 + j * 128;
        o4[j] = a[d] * (v[j] - mean) * inv + b[d];
    }

    if (fa) {
        __syncthreads();
        float s2 = o4[0] + o4[1] + o4[2] + o4[3];
#pragma unroll
        for (int o = 16; o > 0; o >>= 1) s2 += __shfl_xor_sync(0xffffffffu, s2, o);
        if ((t128 & 31) == 0) red[half][t128 >> 5] = s2;
        __syncthreads();
        float mean2 = (red[half][0] + red[half][1] + red[half][2] + red[half][3]) * (1.f / 512.f);
        float ss2 = 0.f;
#pragma unroll
        for (int j = 0; j < 4; j++) {
            float dm = o4[j] - mean2;
            ss2 += dm * dm;
        }
#pragma unroll
        for (int o = 16; o > 0; o >>= 1) ss2 += __shfl_xor_sync(0xffffffffu, ss2, o);
        if ((t128 & 31) == 0) red[half][4 + (t128 >> 5)] = ss2;
        __syncthreads();
        float var2 = (red[half][4] + red[half][5] + red[half][6] + red[half][7]) * (1.f / 511.f);
        float inv2 = 1.f / (sqrtf(var2) + 1e-6f);
#pragma unroll
        for (int j = 0; j < 4; j++) {
            int d = t128 + j * 128;
            o4[j] = fa[d] * (o4[j] - mean2) * inv2 + fb[d];
        }
    }

#pragma unroll
    for (int j = 0; j < 4; j++) {
        int d = t128 + j * 128;
        x[base + d] = o4[j];
        x16[base + d] = __float2half(o4[j]);
    }
}

// ---------------- orchestration ----------------
extern "C" void kernel_launch(void* const* d_in, const int* in_sizes, int n_in,
                              void* d_out, int out_size)
{
    (void)in_sizes; (void)n_in; (void)out_size;
    const int*   input = (const int*)  d_in[0];
    const float* emb   = (const float*)d_in[1];
    const float* Wq    = (const float*)d_in[2];
    const float* Wk    = (const float*)d_in[3];
    const float* Wv    = (const float*)d_in[4];
    const float* Wo    = (const float*)d_in[5];
    const float* w1    = (const float*)d_in[6];
    const float* b1    = (const float*)d_in[7];
    const float* w2    = (const float*)d_in[8];
    const float* b2    = (const float*)d_in[9];
    const float* ln1a  = (const float*)d_in[10];
    const float* ln1b  = (const float*)d_in[11];
    const float* ln2a  = (const float*)d_in[12];
    const float* ln2b  = (const float*)d_in[13];
    const float* fna   = (const float*)d_in[14];
    const float* fnb   = (const float*)d_in[15];
    const float* decW  = (const float*)d_in[16];
    const float* decb  = (const float*)d_in[17];
    float* out = (float*)d_out;

    float *x, *t;
    __nv_bfloat16 *xs, *qkvs, *cs, *ahi, *whi;
    cudaGetSymbolAddress((void**)&x,    g_x);
    cudaGetSymbolAddress((void**)&t,    g_t);
    cudaGetSymbolAddress((void**)&xs,   g_xs);
    cudaGetSymbolAddress((void**)&qkvs, g_qkvs);
    cudaGetSymbolAddress((void**)&cs,   g_cs);
    cudaGetSymbolAddress((void**)&ahi,  g_ahi);
    cudaGetSymbolAddress((void**)&whi,  g_whi);

    __half* x16 = (__half*)xs;
    __half* qkv16 = (__half*)qkvs;
    __half* c16 = (__half*)cs;
    __half* a16 = (__half*)ahi;
    __half* t16 = (__half*)t;
    __half* wh = (__half*)whi;

    cudaFuncSetAttribute(attn_mma, cudaFuncAttributeMaxDynamicSharedMemorySize, ATTN_SMEM);
    cudaFuncSetAttribute(gemm_1t<false, false, 1>, cudaFuncAttributeMaxDynamicSharedMemorySize, GEMM1_SMEM);
    cudaFuncSetAttribute(gemm_1t<true, true, 1>,   cudaFuncAttributeMaxDynamicSharedMemorySize, GEMM1_SMEM);
    cudaFuncSetAttribute(gemm_1t<true, false, 1>,  cudaFuncAttributeMaxDynamicSharedMemorySize, GEMM1_SMEM);
    cudaFuncSetAttribute(gemm_1t<true, false, 0>,  cudaFuncAttributeMaxDynamicSharedMemorySize, GEMM1_SMEM);

    // ---- side stream for weight converts (fork/join; graph-capturable) ----
    cudaStream_t s2;
    cudaStreamCreateWithFlags(&s2, cudaStreamNonBlocking);
    cudaEvent_t eFork, eQKV, eMid, eDec;
    cudaEventCreateWithFlags(&eFork, cudaEventDisableTiming);
    cudaEventCreateWithFlags(&eQKV,  cudaEventDisableTiming);
    cudaEventCreateWithFlags(&eMid,  cudaEventDisableTiming);
    cudaEventCreateWithFlags(&eDec,  cudaEventDisableTiming);

    cudaEventRecord(eFork, 0);
    cudaStreamWaitEvent(s2, eFork, 0);

    cvt16_qkv<<<1024, 256, 0, s2>>>(wh + WQKV0, Wq, 0.125f, 0);
    cvt16_qkv<<<1024, 256, 0, s2>>>(wh + WQKV0, Wk, 1.0f, 131072);
    cvt16_qkv<<<1024, 256, 0, s2>>>(wh + WQKV0, Wv, 1.0f, 262144);
    cudaEventRecord(eQKV, s2);
    cvt16<<<1024, 256, 0, s2>>>(wh + WO0, Wo, 1048576 / 4);
    cvt16<<<4096, 256, 0, s2>>>(wh + W10, w1, 4194304 / 4);
    cvt16<<<4096, 256, 0, s2>>>(wh + W20, w2, 4194304 / 4);
    cudaEventRecord(eMid, s2);
    cvt16<<<16000, 256, 0, s2>>>(wh + WD0, decW, 16384000 / 4);
    cudaEventRecord(eDec, s2);

    // main stream: embed runs concurrently with the cvt chain
    embed_kernel<<<MROWS, 128>>>(x, x16, input, emb);
    cudaStreamWaitEvent(0, eQKV, 0);     // QKV weights ready

    const dim3 gQKV(3 * DMODEL / 256, MROWS / 128);  // (6, 64)
    const dim3 gD(DMODEL / 256, MROWS / 128);        // (2, 64)
    const dim3 gF(DFFN / 256, MROWS / 128);          // (8, 64)
    const dim3 gV(NVOCAB / 256, MROWS / 128);        // (125, 64)
    const dim3 gAttn(LSEQ / 128, BATCH, NHEAD);

    for (int l = 0; l < NLAYER; l++) {
        const size_t qofs = (size_t)l * 1536 * 512;
        const size_t wofs = (size_t)l * DMODEL * DMODEL;
        const size_t f1 = (size_t)l * DFFN * DMODEL;
        const bool last = (l == NLAYER - 1);

        gemm_1t<false, false, 1><<<gQKV, 256, GEMM1_SMEM>>>(
            nullptr, qkv16, x16, wh + WQKV0 + qofs,
            nullptr, MROWS, 3 * DMODEL, DMODEL);

        attn_mma<<<gAttn, 256, ATTN_SMEM>>>(c16, qkv16);

        if (l == 0) cudaStreamWaitEvent(0, eMid, 0);   // Wo/w1/w2 ready

        gemm_1t<false, false, 1><<<gD, 256, GEMM1_SMEM>>>(
            nullptr, t16, c16, wh + WO0 + wofs,
            nullptr, MROWS, DMODEL, DMODEL);
        add_ln_kernel<<<MROWS / 2, 256>>>(x, x16, t16, ln1a + l * DMODEL, ln1b + l * DMODEL,
                                          nullptr, nullptr);

        gemm_1t<true, true, 1><<<gF, 256, GEMM1_SMEM>>>(
            nullptr, a16, x16, wh + W10 + f1,
            b1 + l * DFFN, MROWS, DFFN, DMODEL);
        gemm_1t<true, false, 1><<<gD, 256, GEMM1_SMEM>>>(
            nullptr, t16, a16, wh + W20 + f1,
            b2 + l * DMODEL, MROWS, DMODEL, DFFN);
        add_ln_kernel<<<MROWS / 2, 256>>>(x, x16, t16, ln2a + l * DMODEL, ln2b + l * DMODEL,
                                          last ? fna : nullptr, last ? fnb : nullptr);
    }

    cudaStreamWaitEvent(0, eDec, 0);     // decoder weights ready (join side stream)
    gemm_1t<true, false, 0><<<gV, 256, GEMM1_SMEM>>>(
        out, nullptr, x16, wh + WD0,
        decb, MROWS, NVOCAB, DMODEL);
}

// round 17
// speedup vs baseline: 2.2080x; 1.0049x over previous
#include <cuda_runtime.h>
#include <cuda_bf16.h>
#include <cuda_fp16.h>
#include <math.h>
#include <stdint.h>

#define LSEQ 2048
#define BATCH 4
#define DMODEL 512
#define NHEAD 8
#define DKH 64
#define NLAYER 4
#define DFFN 2048
#define MROWS (LSEQ * BATCH)   // 8192
#define NVOCAB 32000

// ---------------- scratch (device globals; no allocation allowed) ----------------
__device__ float g_t[MROWS * DMODEL];                       // low half used as fp16 t
__device__ __nv_bfloat16 g_xs[2 * MROWS * DMODEL];          // x16 fp16 (half used)
__device__ __nv_bfloat16 g_qkvs[2 * MROWS * 3 * DMODEL];    // qkv fp16 (half used)
__device__ __nv_bfloat16 g_cs[2 * MROWS * DMODEL];          // ctx16 fp16 (half used)
__device__ __nv_bfloat16 g_ahi[MROWS * DFFN];               // ff fp16

// weight storage (fp16 single), element offsets:
#define WQKV0 0                 // fused [NLAYER][1536][512]
#define WO0 3145728
#define W10 4194304
#define W20 8388608
#define WD0 12582912
#define WTOT 28966912
__device__ __nv_bfloat16 g_whi[WTOT];

// ---------------- helpers ----------------
__device__ __forceinline__ uint32_t s2u(const void* p) {
    uint32_t a;
    asm("{ .reg .u64 t; cvta.to.shared.u64 t, %1; cvt.u32.u64 %0, t; }" : "=r"(a) : "l"(p));
    return a;
}
__device__ __forceinline__ void cpa16(uint32_t d, const void* s) {
    asm volatile("cp.async.cg.shared.global [%0], [%1], 16;" :: "r"(d), "l"(s));
}
__device__ __forceinline__ uint32_t h2pack(float x, float y) {
    __half2 t = __floats2half2_rn(x, y);
    return *(uint32_t*)&t;
}

#define LDSM4(r, a) \
    asm volatile("ldmatrix.sync.aligned.m8n8.x4.shared.b16 {%0,%1,%2,%3}, [%4];" \
        : "=r"((r)[0]), "=r"((r)[1]), "=r"((r)[2]), "=r"((r)[3]) : "r"(a))
#define LDSM4T(r, a) \
    asm volatile("ldmatrix.sync.aligned.m8n8.x4.trans.shared.b16 {%0,%1,%2,%3}, [%4];" \
        : "=r"((r)[0]), "=r"((r)[1]), "=r"((r)[2]), "=r"((r)[3]) : "r"(a))

#define MMAF16(c, a, b0, b1) \
    asm volatile("mma.sync.aligned.m16n8k16.row.col.f32.f16.f16.f32 " \
        "{%0,%1,%2,%3}, {%4,%5,%6,%7}, {%8,%9}, {%0,%1,%2,%3};" \
        : "+f"((c)[0]), "+f"((c)[1]), "+f"((c)[2]), "+f"((c)[3]) \
        : "r"((a)[0]), "r"((a)[1]), "r"((a)[2]), "r"((a)[3]), "r"(b0), "r"(b1))

// ---------------- fp32 -> fp16 single weight converts ----------------
__global__ void __launch_bounds__(256) cvt16(__half* __restrict__ dst,
                                             const float* __restrict__ src,
                                             int n4)
{
    int i = blockIdx.x * 256 + threadIdx.x;
    if (i >= n4) return;
    float4 v = ((const float4*)src)[i];
    ((uint32_t*)dst)[2 * i + 0] = h2pack(v.x, v.y);
    ((uint32_t*)dst)[2 * i + 1] = h2pack(v.z, v.w);
}

// strided QKV convert: src [NLAYER][512][512] -> dst layer stride 1536*512
__global__ void __launch_bounds__(256) cvt16_qkv(__half* __restrict__ dst,
                                                 const float* __restrict__ src,
                                                 float scale, int region2)
{
    int i = blockIdx.x * 256 + threadIdx.x;     // 262144 float4s total
    float4 v = ((const float4*)src)[i];
    v.x *= scale; v.y *= scale; v.z *= scale; v.w *= scale;
    int l = i >> 16, w = i & 65535;
    int di = l * 393216 + region2 + 2 * w;      // uint32 units
    ((uint32_t*)dst)[di + 0] = h2pack(v.x, v.y);
    ((uint32_t*)dst)[di + 1] = h2pack(v.z, v.w);
}

// ---------------- fp16 1-term GEMM: C = A * B^T (+bias,+relu) ----------------
// BM=128, BN=256, BK=128; 256 threads; warp 64x64; double buffered.
// OUTM: 0 = fp32 C, 1 = fp16 O16
#define T1S 272                                  // 256B data + 16B pad
#define T1_A_TILE (128 * T1S)                    // 34816
#define T1_B_TILE (256 * T1S)                    // 69632
#define T1_STAGE (T1_A_TILE + T1_B_TILE)         // 104448
#define GEMM1_SMEM (2 * T1_STAGE)                // 208896
#define OFF1_B T1_A_TILE

template <bool BIAS, bool RELU, int OUTM>
__global__ void __launch_bounds__(256) gemm_1t(float* __restrict__ C,
                                               __half* __restrict__ O16,
                                               const __half* __restrict__ A,
                                               const __half* __restrict__ B,
                                               const float* __restrict__ bias,
                                               int M, int N, int K)
{
    extern __shared__ char smem[];
    const uint32_t sb = s2u(smem);
    const int tid = threadIdx.x;
    const int warp = tid >> 5, lane = tid & 31;
    const int bm = blockIdx.y * 128;
    const int bn = blockIdx.x * 256;
    const int warp_m = warp >> 2;
    const int warp_n = warp & 3;
    const int nch = K >> 7;                      // K/128

    const __half* pA = A + (size_t)bm * K;
    const __half* pB = B + (size_t)bn * K;

    auto load_stage = [&](uint32_t st, int k0) {
#pragma unroll
        for (int j = 0; j < 8; j++) {
            int idx = tid + j * 256;
            int r = idx >> 4, seg = idx & 15;
            cpa16(st + r * T1S + seg * 16, pA + (size_t)r * K + k0 + seg * 8);
        }
#pragma unroll
        for (int j = 0; j < 16; j++) {
            int idx = tid + j * 256;
            int r = idx >> 4, seg = idx & 15;
            cpa16(st + OFF1_B + r * T1S + seg * 16, pB + (size_t)r * K + k0 + seg * 8);
        }
    };

    float acc[4][8][4];
#pragma unroll
    for (int i = 0; i < 4; i++)
#pragma unroll
        for (int j = 0; j < 8; j++)
#pragma unroll
            for (int q = 0; q < 4; q++) acc[i][j][q] = 0.f;

    const int g = lane >> 3, lr = lane & 7;
    const int a_row = lr + (g & 1) * 8;
    const int a_k8 = g >> 1;
    const int b_row = lr + (g >> 1) * 8;
    const int b_k8 = g & 1;

    load_stage(sb, 0);
    asm volatile("cp.async.commit_group;" ::: "memory");

    for (int i = 0; i < nch; i++) {
        const uint32_t st = sb + (i & 1) * T1_STAGE;
        __syncthreads();
        if (i + 1 < nch) load_stage(sb + ((i + 1) & 1) * T1_STAGE, (i + 1) * 128);
        asm volatile("cp.async.commit_group;" ::: "memory");
        asm volatile("cp.async.wait_group 1;" ::: "memory");
        __syncthreads();

#pragma unroll
        for (int ks = 0; ks < 8; ks++) {
            uint32_t ah[4][4];
#pragma unroll
            for (int mi = 0; mi < 4; mi++) {
                uint32_t aaddr = st + (warp_m * 64 + mi * 16 + a_row) * T1S +
                                 ks * 32 + a_k8 * 16;
                LDSM4(ah[mi], aaddr);
            }
#pragma unroll
            for (int ng = 0; ng < 4; ng++) {
                uint32_t bfr[4];
                uint32_t baddr = st + OFF1_B + (warp_n * 64 + ng * 16 + b_row) * T1S +
                                 ks * 32 + b_k8 * 16;
                LDSM4(bfr, baddr);
#pragma unroll
                for (int mi = 0; mi < 4; mi++) {
                    MMAF16(acc[mi][2 * ng], ah[mi], bfr[0], bfr[1]);
                    MMAF16(acc[mi][2 * ng + 1], ah[mi], bfr[2], bfr[3]);
                }
            }
        }
    }

    const int tm = lane >> 2, tn = (lane & 3) * 2;
#pragma unroll
    for (int mi = 0; mi < 4; mi++) {
#pragma unroll
        for (int nj = 0; nj < 8; nj++) {
            const float* a4 = acc[mi][nj];
            int row0 = bm + warp_m * 64 + mi * 16 + tm;
            int col = bn + warp_n * 64 + nj * 8 + tn;
            float b0 = 0.f, b1 = 0.f;
            if (BIAS) { b0 = bias[col]; b1 = bias[col + 1]; }
            float v0 = a4[0] + b0, v1 = a4[1] + b1;
            float v2 = a4[2] + b0, v3 = a4[3] + b1;
            if (RELU) {
                v0 = fmaxf(v0, 0.f); v1 = fmaxf(v1, 0.f);
                v2 = fmaxf(v2, 0.f); v3 = fmaxf(v3, 0.f);
            }
            if (OUTM == 0) {
                *(float2*)(C + (size_t)row0 * N + col) = make_float2(v0, v1);
                *(float2*)(C + (size_t)(row0 + 8) * N + col) = make_float2(v2, v3);
            } else {
                *(uint32_t*)(O16 + (size_t)row0 * N + col) = h2pack(v0, v1);
                *(uint32_t*)(O16 + (size_t)(row0 + 8) * N + col) = h2pack(v2, v3);
            }
        }
    }
}

// ---------------- embedding + positional encoding (fp16 out only) ----------------
__global__ void __launch_bounds__(128) embed_kernel(__half* __restrict__ x16,
                                                    const int* __restrict__ tok,
                                                    const float* __restrict__ emb)
{
    int m = blockIdx.x;
    int l = m >> 2;
    int t = tok[m];
    const float sq = 22.627416997969522f;
    const double nlog = 9.210340371976184;
#pragma unroll
    for (int j = 0; j < 4; j++) {
        int d = threadIdx.x + j * 128;
        int i = d >> 1;
        float freqf = (float)exp(-(double)(2 * i) * (nlog / 512.0));
        float angf = (float)l * freqf;
        double ang = (double)angf;
        float pe = (d & 1) ? (float)cos(ang) : (float)sin(ang);
        float v = emb[(size_t)t * DMODEL + d] * sq + pe;
        x16[(size_t)m * DMODEL + d] = __float2half(v);
    }
}

// ---------------- fp16 flash attention (causal, 1-term), 64-row KV stages --------
// CTA order reversed: heavy (high-bx) diagonal tiles scheduled first.
#define QKVSTR 1536
#define AT_S 144
#define AQ_B (128 * AT_S)          // 18432
#define AKV_TILE (64 * AT_S)       // 9216
#define AKV_STAGE (2 * AKV_TILE)   // 18432 (K + V)
#define ATTN_SMEM (AQ_B + 2 * AKV_STAGE)   // 55296 -> 2 CTAs/SM

__global__ void __launch_bounds__(256) attn_mma(
    __half* __restrict__ ctx16,
    const __half* __restrict__ qkv16)
{
    extern __shared__ char smem[];
    const uint32_t sb = s2u(smem);
    const int tid = threadIdx.x, warp = tid >> 5, lane = tid & 31;
    const int bx = gridDim.x - 1 - blockIdx.x;   // reversed: heavy tiles first
    const int b = blockIdx.y, h = blockIdx.z;
    const int l0 = bx * 128;
    const int ntiles = 2 * bx + 2;

    const uint32_t sQ = sb;
    const uint32_t sKV = sb + AQ_B;

    // load Q tile: 128 rows x 8 segs of 16B
#pragma unroll
    for (int t = 0; t < 4; t++) {
        int idx = tid + t * 256;
        int row = idx >> 3, seg = idx & 7;
        cpa16(sQ + row * AT_S + seg * 16,
              qkv16 + ((size_t)(l0 + row) * 4 + b) * QKVSTR + h * 64 + seg * 8);
    }
    asm volatile("cp.async.commit_group;" ::: "memory");

    auto load_kv = [&](int s, int jt) {
        uint32_t st = sKV + s * AKV_STAGE;
#pragma unroll
        for (int t = 0; t < 4; t++) {
            int idx = tid + t * 256;
            int arr = idx >> 9;            // 0=K, 1=V
            int row = (idx >> 3) & 63;
            int seg = idx & 7;
            int coff = 512 + arr * 512;
            cpa16(st + arr * AKV_TILE + row * AT_S + seg * 16,
                  qkv16 + ((size_t)(jt * 64 + row) * 4 + b) * QKVSTR + coff + h * 64 + seg * 8);
        }
    };
    load_kv(0, 0);
    asm volatile("cp.async.commit_group;" ::: "memory");

    const int a_row = (lane & 7) + ((lane >> 3) & 1) * 8;
    const int a_k8 = lane >> 4;
    const int b_row = (lane & 7) + (lane >> 4) * 8;
    const int b_k8 = (lane >> 3) & 1;

    uint32_t qf[4][4];
    float ctx[8][4];
#pragma unroll
    for (int i = 0; i < 8; i++)
#pragma unroll
        for (int j = 0; j < 4; j++) ctx[i][j] = 0.f;
    float m0 = -INFINITY, m1 = -INFINITY, l0s = 0.f, l1s = 0.f;

    for (int jt = 0; jt < ntiles; jt++) {
        const uint32_t st = sKV + (jt & 1) * AKV_STAGE;
        __syncthreads();
        if (jt + 1 < ntiles) {
            load_kv((jt + 1) & 1, jt + 1);
            asm volatile("cp.async.commit_group;" ::: "memory");
            asm volatile("cp.async.wait_group 1;" ::: "memory");
        } else {
            asm volatile("cp.async.wait_group 0;" ::: "memory");
        }
        __syncthreads();

        if (jt == 0) {
#pragma unroll
            for (int kb = 0; kb < 4; kb++) {
                uint32_t qa = sQ + (warp * 16 + a_row) * AT_S + (kb * 2 + a_k8) * 16;
                LDSM4(qf[kb], qa);
            }
        }

        // S = Q K^T (1 term)
        float S[8][4];
#pragma unroll
        for (int i = 0; i < 8; i++)
#pragma unroll
            for (int j = 0; j < 4; j++) S[i][j] = 0.f;
#pragma unroll
        for (int kb = 0; kb < 4; kb++) {
#pragma unroll
            for (int ng = 0; ng < 4; ng++) {
                uint32_t kf[4];
                uint32_t ka = st + (ng * 16 + b_row) * AT_S + (kb * 2 + b_k8) * 16;
                LDSM4(kf, ka);
                int nb = ng * 2;
                MMAF16(S[nb], qf[kb], kf[0], kf[1]);
                MMAF16(S[nb + 1], qf[kb], kf[2], kf[3]);
            }
        }

        const int qr0 = l0 + warp * 16 + (lane >> 2);
        const int qr1 = qr0 + 8;
        if (jt >= ntiles - 2) {
#pragma unroll
            for (int nb = 0; nb < 8; nb++) {
                int c = jt * 64 + nb * 8 + 2 * (lane & 3);
                if (c > qr0) S[nb][0] = -INFINITY;
                if (c + 1 > qr0) S[nb][1] = -INFINITY;
                if (c > qr1) S[nb][2] = -INFINITY;
                if (c + 1 > qr1) S[nb][3] = -INFINITY;
            }
        }

        // online softmax
        float mx0 = -INFINITY, mx1 = -INFINITY;
#pragma unroll
        for (int nb = 0; nb < 8; nb++) {
            mx0 = fmaxf(mx0, fmaxf(S[nb][0], S[nb][1]));
            mx1 = fmaxf(mx1, fmaxf(S[nb][2], S[nb][3]));
        }
        mx0 = fmaxf(mx0, __shfl_xor_sync(0xffffffffu, mx0, 1));
        mx0 = fmaxf(mx0, __shfl_xor_sync(0xffffffffu, mx0, 2));
        mx1 = fmaxf(mx1, __shfl_xor_sync(0xffffffffu, mx1, 1));
        mx1 = fmaxf(mx1, __shfl_xor_sync(0xffffffffu, mx1, 2));
        float nm0 = fmaxf(m0, mx0), nm1 = fmaxf(m1, mx1);
        float c0 = __expf(m0 - nm0), c1 = __expf(m1 - nm1);
        m0 = nm0; m1 = nm1;
        float s0 = 0.f, s1 = 0.f;
#pragma unroll
        for (int nb = 0; nb < 8; nb++) {
            S[nb][0] = __expf(S[nb][0] - nm0);
            S[nb][1] = __expf(S[nb][1] - nm0);
            S[nb][2] = __expf(S[nb][2] - nm1);
            S[nb][3] = __expf(S[nb][3] - nm1);
            s0 += S[nb][0] + S[nb][1];
            s1 += S[nb][2] + S[nb][3];
        }
        s0 += __shfl_xor_sync(0xffffffffu, s0, 1);
        s0 += __shfl_xor_sync(0xffffffffu, s0, 2);
        s1 += __shfl_xor_sync(0xffffffffu, s1, 1);
        s1 += __shfl_xor_sync(0xffffffffu, s1, 2);
        l0s = l0s * c0 + s0;
        l1s = l1s * c1 + s1;
#pragma unroll
        for (int nb = 0; nb < 8; nb++) {
            ctx[nb][0] *= c0; ctx[nb][1] *= c0;
            ctx[nb][2] *= c1; ctx[nb][3] *= c1;
        }

        // P fragments (fp16, values in [0,1])
        uint32_t ph[4][4];
#pragma unroll
        for (int kb = 0; kb < 4; kb++) {
            const float* sA = S[2 * kb];
            const float* sB = S[2 * kb + 1];
            ph[kb][0] = h2pack(sA[0], sA[1]);
            ph[kb][1] = h2pack(sA[2], sA[3]);
            ph[kb][2] = h2pack(sB[0], sB[1]);
            ph[kb][3] = h2pack(sB[2], sB[3]);
        }

        // ctx += P V (1 term); V via ldmatrix.trans
        const uint32_t vrow = (lane & 7) + ((lane >> 3) & 1) * 8;
        const uint32_t vcol16 = (lane >> 4) * 16;
#pragma unroll
        for (int kb = 0; kb < 4; kb++) {
#pragma unroll
            for (int ngd = 0; ngd < 4; ngd++) {
                uint32_t vb[4];
                uint32_t va = st + AKV_TILE + (kb * 16 + vrow) * AT_S + ngd * 32 + vcol16;
                LDSM4T(vb, va);
                int nd = ngd * 2;
                MMAF16(ctx[nd], ph[kb], vb[0], vb[1]);
                MMAF16(ctx[nd + 1], ph[kb], vb[2], vb[3]);
            }
        }
    }

    float inv0 = 1.f / l0s, inv1 = 1.f / l1s;
    const size_t mg0 = (size_t)(l0 + warp * 16 + (lane >> 2)) * 4 + b;
    const size_t mg1 = mg0 + 32;
#pragma unroll
    for (int nd = 0; nd < 8; nd++) {
        int col = h * 64 + nd * 8 + 2 * (lane & 3);
        *(uint32_t*)(ctx16 + mg0 * 512 + col) = h2pack(ctx[nd][0] * inv0, ctx[nd][1] * inv0);
        *(uint32_t*)(ctx16 + mg1 * 512 + col) = h2pack(ctx[nd][2] * inv1, ctx[nd][3] * inv1);
    }
}

// ---------------- fused residual-add + LayerNorm (2 rows/block, fp16 in/out) ----
// fp16 residual stream: reads x16 + y16, writes x16 (+ optional final LN).
__global__ void __launch_bounds__(256) add_ln_kernel(__half* __restrict__ x16,
                                                     const __half* __restrict__ y,
                                                     const float* __restrict__ a,
                                                     const float* __restrict__ b,
                                                     const float* __restrict__ fa,
                                                     const float* __restrict__ fb)
{
    const int tid = threadIdx.x;
    const int half = tid >> 7;           // 0 or 1 (row within block)
    const int t128 = tid & 127;
    const int m = blockIdx.x * 2 + half;
    const size_t base = (size_t)m * DMODEL;
    __shared__ float red[2][8];

    float v[4];
#pragma unroll
    for (int j = 0; j < 4; j++) {
        int d = t128 + j * 128;
        v[j] = __half2float(x16[base + d]) + __half2float(y[base + d]);
    }
    float s = v[0] + v[1] + v[2] + v[3];
#pragma unroll
    for (int o = 16; o > 0; o >>= 1) s += __shfl_xor_sync(0xffffffffu, s, o);
    if ((t128 & 31) == 0) red[half][t128 >> 5] = s;
    __syncthreads();
    float mean = (red[half][0] + red[half][1] + red[half][2] + red[half][3]) * (1.f / 512.f);

    float ss = 0.f;
#pragma unroll
    for (int j = 0; j < 4; j++) {
        float dm = v[j] - mean;
        ss += dm * dm;
    }
#pragma unroll
    for (int o = 16; o > 0; o >>= 1) ss += __shfl_xor_sync(0xffffffffu, ss, o);
    if ((t128 & 31) == 0) red[half][4 + (t128 >> 5)] = ss;
    __syncthreads();
    float var = (red[half][4] + red[half][5] + red[half][6] + red[half][7]) * (1.f / 511.f);
    float inv = 1.f / (sqrtf(var) + 1e-6f);

    float o4[4];
#pragma unroll
    for (int j = 0; j < 4; j++) {
        int d = t128 + j * 128;
        o4[j] = a[d] * (v[j] - mean) * inv + b[d];
    }

    if (fa) {
        __syncthreads();
        float s2 = o4[0] + o4[1] + o4[2] + o4[3];
#pragma unroll
        for (int o = 16; o > 0; o >>= 1) s2 += __shfl_xor_sync(0xffffffffu, s2, o);
        if ((t128 & 31) == 0) red[half][t128 >> 5] = s2;
        __syncthreads();
        float mean2 = (red[half][0] + red[half][1] + red[half][2] + red[half][3]) * (1.f / 512.f);
        float ss2 = 0.f;
#pragma unroll
        for (int j = 0; j < 4; j++) {
            float dm = o4[j] - mean2;
            ss2 += dm * dm;
        }
#pragma unroll
        for (int o = 16; o > 0; o >>= 1) ss2 += __shfl_xor_sync(0xffffffffu, ss2, o);
        if ((t128 & 31) == 0) red[half][4 + (t128 >> 5)] = ss2;
        __syncthreads();
        float var2 = (red[half][4] + red[half][5] + red[half][6] + red[half][7]) * (1.f / 511.f);
        float inv2 = 1.f / (sqrtf(var2) + 1e-6f);
#pragma unroll
        for (int j = 0; j < 4; j++) {
            int d = t128 + j * 128;
            o4[j] = fa[d] * (o4[j] - mean2) * inv2 + fb[d];
        }
    }

#pragma unroll
    for (int j = 0; j < 4; j++) {
        int d = t128 + j * 128;
        x16[base + d] = __float2half(o4[j]);
    }
}

// ---------------- orchestration ----------------
extern "C" void kernel_launch(void* const* d_in, const int* in_sizes, int n_in,
                              void* d_out, int out_size)
{
    (void)in_sizes; (void)n_in; (void)out_size;
    const int*   input = (const int*)  d_in[0];
    const float* emb   = (const float*)d_in[1];
    const float* Wq    = (const float*)d_in[2];
    const float* Wk    = (const float*)d_in[3];
    const float* Wv    = (const float*)d_in[4];
    const float* Wo    = (const float*)d_in[5];
    const float* w1    = (const float*)d_in[6];
    const float* b1    = (const float*)d_in[7];
    const float* w2    = (const float*)d_in[8];
    const float* b2    = (const float*)d_in[9];
    const float* ln1a  = (const float*)d_in[10];
    const float* ln1b  = (const float*)d_in[11];
    const float* ln2a  = (const float*)d_in[12];
    const float* ln2b  = (const float*)d_in[13];
    const float* fna   = (const float*)d_in[14];
    const float* fnb   = (const float*)d_in[15];
    const float* decW  = (const float*)d_in[16];
    const float* decb  = (const float*)d_in[17];
    float* out = (float*)d_out;

    float *t;
    __nv_bfloat16 *xs, *qkvs, *cs, *ahi, *whi;
    cudaGetSymbolAddress((void**)&t,    g_t);
    cudaGetSymbolAddress((void**)&xs,   g_xs);
    cudaGetSymbolAddress((void**)&qkvs, g_qkvs);
    cudaGetSymbolAddress((void**)&cs,   g_cs);
    cudaGetSymbolAddress((void**)&ahi,  g_ahi);
    cudaGetSymbolAddress((void**)&whi,  g_whi);

    __half* x16 = (__half*)xs;
    __half* qkv16 = (__half*)qkvs;
    __half* c16 = (__half*)cs;
    __half* a16 = (__half*)ahi;
    __half* t16 = (__half*)t;
    __half* wh = (__half*)whi;

    cudaFuncSetAttribute(attn_mma, cudaFuncAttributeMaxDynamicSharedMemorySize, ATTN_SMEM);
    cudaFuncSetAttribute(gemm_1t<false, false, 1>, cudaFuncAttributeMaxDynamicSharedMemorySize, GEMM1_SMEM);
    cudaFuncSetAttribute(gemm_1t<true, true, 1>,   cudaFuncAttributeMaxDynamicSharedMemorySize, GEMM1_SMEM);
    cudaFuncSetAttribute(gemm_1t<true, false, 1>,  cudaFuncAttributeMaxDynamicSharedMemorySize, GEMM1_SMEM);
    cudaFuncSetAttribute(gemm_1t<true, false, 0>,  cudaFuncAttributeMaxDynamicSharedMemorySize, GEMM1_SMEM);

    // ---- side stream for weight converts (fork/join; graph-capturable) ----
    cudaStream_t s2;
    cudaStreamCreateWithFlags(&s2, cudaStreamNonBlocking);
    cudaEvent_t eFork, eQKV, eMid, eDec;
    cudaEventCreateWithFlags(&eFork, cudaEventDisableTiming);
    cudaEventCreateWithFlags(&eQKV,  cudaEventDisableTiming);
    cudaEventCreateWithFlags(&eMid,  cudaEventDisableTiming);
    cudaEventCreateWithFlags(&eDec,  cudaEventDisableTiming);

    cudaEventRecord(eFork, 0);
    cudaStreamWaitEvent(s2, eFork, 0);

    cvt16_qkv<<<1024, 256, 0, s2>>>(wh + WQKV0, Wq, 0.125f, 0);
    cvt16_qkv<<<1024, 256, 0, s2>>>(wh + WQKV0, Wk, 1.0f, 131072);
    cvt16_qkv<<<1024, 256, 0, s2>>>(wh + WQKV0, Wv, 1.0f, 262144);
    cudaEventRecord(eQKV, s2);
    cvt16<<<1024, 256, 0, s2>>>(wh + WO0, Wo, 1048576 / 4);
    cvt16<<<4096, 256, 0, s2>>>(wh + W10, w1, 4194304 / 4);
    cvt16<<<4096, 256, 0, s2>>>(wh + W20, w2, 4194304 / 4);
    cudaEventRecord(eMid, s2);
    cvt16<<<16000, 256, 0, s2>>>(wh + WD0, decW, 16384000 / 4);
    cudaEventRecord(eDec, s2);

    // main stream: embed runs concurrently with the cvt chain
    embed_kernel<<<MROWS, 128>>>(x16, input, emb);
    cudaStreamWaitEvent(0, eQKV, 0);     // QKV weights ready

    const dim3 gQKV(3 * DMODEL / 256, MROWS / 128);  // (6, 64)
    const dim3 gD(DMODEL / 256, MROWS / 128);        // (2, 64)
    const dim3 gF(DFFN / 256, MROWS / 128);          // (8, 64)
    const dim3 gV(NVOCAB / 256, MROWS / 128);        // (125, 64)
    const dim3 gAttn(LSEQ / 128, BATCH, NHEAD);

    for (int l = 0; l < NLAYER; l++) {
        const size_t qofs = (size_t)l * 1536 * 512;
        const size_t wofs = (size_t)l * DMODEL * DMODEL;
        const size_t f1 = (size_t)l * DFFN * DMODEL;
        const bool last = (l == NLAYER - 1);

        gemm_1t<false, false, 1><<<gQKV, 256, GEMM1_SMEM>>>(
            nullptr, qkv16, x16, wh + WQKV0 + qofs,
            nullptr, MROWS, 3 * DMODEL, DMODEL);

        attn_mma<<<gAttn, 256, ATTN_SMEM>>>(c16, qkv16);

        if (l == 0) cudaStreamWaitEvent(0, eMid, 0);   // Wo/w1/w2 ready

        gemm_1t<false, false, 1><<<gD, 256, GEMM1_SMEM>>>(
            nullptr, t16, c16, wh + WO0 + wofs,
            nullptr, MROWS, DMODEL, DMODEL);
        add_ln_kernel<<<MROWS / 2, 256>>>(x16, t16, ln1a + l * DMODEL, ln1b + l * DMODEL,
                                          nullptr, nullptr);

        gemm_1t<true, true, 1><<<gF, 256, GEMM1_SMEM>>>(
            nullptr, a16, x16, wh + W10 + f1,
            b1 + l * DFFN, MROWS, DFFN, DMODEL);
        gemm_1t<true, false, 1><<<gD, 256, GEMM1_SMEM>>>(
            nullptr, t16, a16, wh + W20 + f1,
            b2 + l * DMODEL, MROWS, DMODEL, DFFN);
        add_ln_kernel<<<MROWS / 2, 256>>>(x16, t16, ln2a + l * DMODEL, ln2b + l * DMODEL,
                                          last ? fna : nullptr, last ? fnb : nullptr);
    }

    cudaStreamWaitEvent(0, eDec, 0);     // decoder weights ready (join side stream)
    gemm_1t<true, false, 0><<<gV, 256, GEMM1_SMEM>>>(
        out, nullptr, x16, wh + WD0,
        decb, MROWS, NVOCAB, DMODEL);
}